// round 1
// baseline (speedup 1.0000x reference)
#include <cuda_runtime.h>
#include <math.h>

// ---------------------------------------------------------------------------
// Problem constants
// ---------------------------------------------------------------------------
namespace {
constexpr int TNn = 32768;   // total nodes  (B*N)
constexpr int C   = 256;     // channels
constexpr int E   = 524288;  // edges
constexpr int Bg  = 64;      // graphs
constexpr int Nn  = 512;     // nodes per graph
constexpr int H   = 4;       // heads
constexpr int DH  = 64;      // head dim
constexpr int MF  = 266;     // Performer random features
constexpr int C2  = 512;     // MLP hidden
constexpr int L   = 5;       // layers
constexpr int NBH = Bg * H;  // 256 attention batches

// scratch layout (floats)
constexpr long SZ_NC    = (long)TNn * C;                 // 8,388,608
constexpr long OFF_ATOMS = 0;
constexpr long OFF_EA    = OFF_ATOMS + SZ_NC;
constexpr long OFF_H     = OFF_EA + (long)E * C;
constexpr long OFF_T1    = OFF_H + SZ_NC;
constexpr long OFF_TMP   = OFF_T1 + (long)TNn * C2;
constexpr long OFF_HLOC  = OFF_TMP + SZ_NC;
constexpr long OFF_Q     = OFF_HLOC + SZ_NC;
constexpr long OFF_K     = OFF_Q + SZ_NC;
constexpr long OFF_V     = OFF_K + SZ_NC;
constexpr long OFF_QR    = OFF_V + SZ_NC;
constexpr long OFF_KR    = OFF_QR + SZ_NC;
constexpr long OFF_VR    = OFF_KR + SZ_NC;
constexpr long OFF_QP    = OFF_VR + SZ_NC;
constexpr long OFF_KP    = OFF_QP + (long)NBH * Nn * MF;
constexpr long OFF_KSUM  = OFF_KP + (long)NBH * Nn * MF;
constexpr long OFF_CTX   = OFF_KSUM + (long)NBH * MF;
constexpr long OFF_DINV  = OFF_CTX + (long)NBH * MF * DH;
constexpr long OFF_ATTR  = OFF_DINV + (long)NBH * Nn;
constexpr long OFF_ATT   = OFF_ATTR + SZ_NC;
constexpr long OFF_HATT  = OFF_ATT + SZ_NC;
constexpr long OFF_OUT   = OFF_HATT + SZ_NC;
constexpr long OFF_XL    = OFF_OUT + SZ_NC;
constexpr long SCRATCH_TOTAL = OFF_XL + (long)TNn * 11;
}  // namespace

__device__ float g_scratch[SCRATCH_TOTAL];   // ~1.37 GB static scratch (no cudaMalloc)

// ---------------------------------------------------------------------------
// Generic guarded SGEMM.
//   MODE: 0 = NN (A[M][K], B[K][N])   1 = NT (A[M][K], B[N][K])   2 = TN (A[K][M], B[K][N])
//   ACT : 0 = none  1 = exact GELU  2 = relu + 1e-3  3 = per-row scale (rs)
//   Batched via gridDim.z with element strides sA/sB/sC (sRS for rowscale).
//   BM=128, BK=8, 256 threads, 8 x (BN_/16) microtile.
// ---------------------------------------------------------------------------
template<int BN_, int MODE, int ACT>
__global__ __launch_bounds__(256)
void gemm_k(const float* __restrict__ A, const float* __restrict__ Bm,
            const float* __restrict__ bias, const float* __restrict__ rs,
            float* __restrict__ Cm,
            int Mr, int Nc, int K, int lda, int ldb, int ldc,
            long sA, long sB, long sC, long sRS)
{
    constexpr int BM = 128, BK = 8;
    constexpr int TNC = BN_ / 16;   // 8 (BN=128) or 4 (BN=64)

    const int z = blockIdx.z;
    A  += (long)z * sA;
    Bm += (long)z * sB;
    Cm += (long)z * sC;

    __shared__ float As[BK][BM];
    __shared__ float Bs[BK][BN_];

    const int tid = threadIdx.x;
    const int tx = tid & 15;
    const int ty = tid >> 4;
    const int rowBase = blockIdx.y * BM;
    const int colBase = blockIdx.x * BN_;

    float acc[8][TNC];
    #pragma unroll
    for (int i = 0; i < 8; i++)
        #pragma unroll
        for (int j = 0; j < TNC; j++) acc[i][j] = 0.f;

    for (int kt = 0; kt < K; kt += BK) {
        // ---- A tile -> As[k][m] ----
        if (MODE != 2) {                       // A row-major [M][K]
            int ar = tid >> 1;                 // 0..127 (m within tile)
            int ac = (tid & 1) * 4;            // 0 or 4 (k within tile)
            int gm = rowBase + ar;
            bool rowok = (gm < Mr);
            const float* ap = A + (long)gm * lda + kt + ac;
            #pragma unroll
            for (int i = 0; i < 4; i++) {
                int gk = kt + ac + i;
                As[ac + i][ar] = (rowok && gk < K) ? ap[i] : 0.f;
            }
        } else {                               // TN: A is [K][M]
            int kr = tid >> 5;                 // 0..7
            int m0 = (tid & 31) * 4;
            int gk = kt + kr;
            bool kok = (gk < K);
            const float* ap = A + (long)gk * lda + rowBase + m0;
            #pragma unroll
            for (int i = 0; i < 4; i++) {
                int gm = rowBase + m0 + i;
                As[kr][m0 + i] = (kok && gm < Mr) ? ap[i] : 0.f;
            }
        }
        // ---- B tile -> Bs[k][n] ----
        if (MODE == 1) {                       // NT: B is [N][K] (only BN_==128 used)
            int br = tid >> 1;
            int bc = (tid & 1) * 4;
            int gn = colBase + br;
            bool nok = (gn < Nc);
            const float* bp = Bm + (long)gn * ldb + kt + bc;
            #pragma unroll
            for (int i = 0; i < 4; i++) {
                int gk = kt + bc + i;
                Bs[bc + i][br] = (nok && gk < K) ? bp[i] : 0.f;
            }
        } else {                               // NN/TN: B is [K][N]
            constexpr int PERB = BK * BN_ / 256;   // 4 or 2
            int idx = tid * PERB;
            int kr = idx / BN_;
            int n0 = idx % BN_;
            int gk = kt + kr;
            bool kok = (gk < K);
            const float* bp = Bm + (long)gk * ldb + colBase + n0;
            #pragma unroll
            for (int i = 0; i < PERB; i++) {
                int gn = colBase + n0 + i;
                Bs[kr][n0 + i] = (kok && gn < Nc) ? bp[i] : 0.f;
            }
        }
        __syncthreads();

        #pragma unroll
        for (int k = 0; k < BK; k++) {
            float a[8], b[TNC];
            #pragma unroll
            for (int i = 0; i < 8; i++) a[i] = As[k][ty * 8 + i];
            #pragma unroll
            for (int j = 0; j < TNC; j++) b[j] = Bs[k][tx * TNC + j];
            #pragma unroll
            for (int i = 0; i < 8; i++)
                #pragma unroll
                for (int j = 0; j < TNC; j++)
                    acc[i][j] = fmaf(a[i], b[j], acc[i][j]);
        }
        __syncthreads();
    }

    // ---- epilogue ----
    #pragma unroll
    for (int i = 0; i < 8; i++) {
        int gr = rowBase + ty * 8 + i;
        if (gr >= Mr) continue;
        float scale = 1.f;
        if (ACT == 3) scale = rs[(long)z * sRS + gr];
        float* crow = Cm + (long)gr * ldc;
        #pragma unroll
        for (int j = 0; j < TNC; j++) {
            int gc = colBase + tx * TNC + j;
            if (gc >= Nc) continue;
            float v = acc[i][j];
            if (bias) v += bias[gc];
            if (ACT == 1)      v = v * normcdff(v);           // exact GELU
            else if (ACT == 2) v = fmaxf(v, 0.f) + 1e-3f;     // relu + EPS_K
            else if (ACT == 3) v *= scale;                    // d_inv row scale
            crow[gc] = v;
        }
    }
}

// ---------------------------------------------------------------------------
// Elementwise / reduction kernels
// ---------------------------------------------------------------------------
__global__ void log1p_k(const float* __restrict__ x, float* __restrict__ o, int n) {
    int i = blockIdx.x * 256 + threadIdx.x;
    if (i < n) o[i] = log1pf(x[i]);
}

__global__ void copy_k(float* __restrict__ dst, const float* __restrict__ src, long n4) {
    long i = blockIdx.x * 256L + threadIdx.x;
    if (i < n4) ((float4*)dst)[i] = ((const float4*)src)[i];
}

__global__ void add_k(const float* __restrict__ a, const float* __restrict__ b,
                      float* __restrict__ o, long n4) {
    long i = blockIdx.x * 256L + threadIdx.x;
    if (i < n4) {
        float4 x = ((const float4*)a)[i], y = ((const float4*)b)[i];
        x.x += y.x; x.y += y.y; x.z += y.z; x.w += y.w;
        ((float4*)o)[i] = x;
    }
}

// GINE message + scatter-add: aggr[dst] += relu(atoms[src] + ea[e])
// one warp per edge, 8 channels per lane; skip atomic when relu output is 0.
__global__ __launch_bounds__(256)
void scatter_k(const float* __restrict__ atoms, const float* __restrict__ ea,
               const int* __restrict__ ei, float* __restrict__ aggr) {
    int g = blockIdx.x * 256 + threadIdx.x;
    int e = g >> 5, lane = g & 31;
    if (e >= E) return;
    int s = ei[e];
    int d = ei[E + e];
    const float4* ar = reinterpret_cast<const float4*>(atoms + (long)s * C) + lane * 2;
    const float4* er = reinterpret_cast<const float4*>(ea + (long)e * C) + lane * 2;
    float* out = aggr + (long)d * C + lane * 8;
    #pragma unroll
    for (int t = 0; t < 2; t++) {
        float4 a = ar[t], ev = er[t];
        float m;
        m = a.x + ev.x; if (m > 0.f) atomicAdd(out + t * 4 + 0, m);
        m = a.y + ev.y; if (m > 0.f) atomicAdd(out + t * 4 + 1, m);
        m = a.z + ev.z; if (m > 0.f) atomicAdd(out + t * 4 + 2, m);
        m = a.w + ev.w; if (m > 0.f) atomicAdd(out + t * 4 + 3, m);
    }
}

// out = LayerNorm(a + b) * g + be   (one warp per row of C=256)
__global__ __launch_bounds__(256)
void add_ln_k(const float* __restrict__ a, const float* __restrict__ b,
              const float* __restrict__ g, const float* __restrict__ be,
              float* __restrict__ o) {
    int w = (blockIdx.x * 256 + threadIdx.x) >> 5;
    int lane = threadIdx.x & 31;
    if (w >= TNn) return;
    const float* ar = a + (long)w * C;
    const float* br = b + (long)w * C;
    float v[8]; float s = 0.f, s2 = 0.f;
    #pragma unroll
    for (int i = 0; i < 8; i++) {
        int c = lane + i * 32;
        float t = ar[c] + br[c];
        v[i] = t; s += t; s2 += t * t;
    }
    #pragma unroll
    for (int off = 16; off; off >>= 1) {
        s  += __shfl_xor_sync(0xffffffffu, s, off);
        s2 += __shfl_xor_sync(0xffffffffu, s2, off);
    }
    float mu = s * (1.f / C);
    float var = s2 * (1.f / C) - mu * mu;
    float rstd = rsqrtf(var + 1e-5f);
    float* orow = o + (long)w * C;
    #pragma unroll
    for (int i = 0; i < 8; i++) {
        int c = lane + i * 32;
        orow[c] = (v[i] - mu) * rstd * g[c] + be[c];
    }
}

// [TN, H*DH] -> [bh][n][d]  for q,k,v at once
__global__ void permute_qkv_k(const float* __restrict__ q, const float* __restrict__ k,
                              const float* __restrict__ v,
                              float* __restrict__ qr, float* __restrict__ kr,
                              float* __restrict__ vr) {
    long i = blockIdx.x * 256L + threadIdx.x;
    if (i >= SZ_NC) return;
    int d = (int)(i & 63);
    long t = i >> 6;
    int n = (int)(t % Nn); t /= Nn;
    int h = (int)(t % H);
    int b = (int)(t / H);
    long src = ((long)b * Nn + n) * C + h * DH + d;
    qr[i] = q[src]; kr[i] = k[src]; vr[i] = v[src];
}

// [bh][n][d] -> [TN, H*DH]
__global__ void permute_att_k(const float* __restrict__ attr, float* __restrict__ att) {
    long i = blockIdx.x * 256L + threadIdx.x;   // dest index
    if (i >= SZ_NC) return;
    int c = (int)(i & (C - 1));
    long r = i >> 8;                // C = 256
    int n = (int)(r % Nn);
    int b = (int)(r / Nn);
    int h = c >> 6;
    int d = c & 63;
    long src = (((long)(b * H + h)) * Nn + n) * DH + d;
    att[i] = attr[src];
}

// ksum[bh][m] = sum_n kp[bh][n][m]
__global__ void ksum_k(const float* __restrict__ kp, float* __restrict__ ks) {
    int bh = blockIdx.y;
    int m = blockIdx.x * 256 + threadIdx.x;
    if (m >= MF) return;
    const float* p = kp + (long)bh * Nn * MF + m;
    float s = 0.f;
    for (int n = 0; n < Nn; n++) s += p[(long)n * MF];
    ks[bh * MF + m] = s;
}

// dinv[bh][n] = 1 / dot(qp[bh][n][:], ksum[bh][:])
__global__ __launch_bounds__(256)
void dinv_k(const float* __restrict__ qp, const float* __restrict__ ks,
            float* __restrict__ dinv) {
    __shared__ float kss[MF];
    int bh = blockIdx.y;
    for (int m = threadIdx.x; m < MF; m += 256) kss[m] = ks[bh * MF + m];
    __syncthreads();
    int warp = threadIdx.x >> 5, lane = threadIdx.x & 31;
    int n = blockIdx.x * 8 + warp;
    const float* q = qp + ((long)bh * Nn + n) * MF;
    float s = 0.f;
    for (int m = lane; m < MF; m += 32) s += q[m] * kss[m];
    #pragma unroll
    for (int off = 16; off; off >>= 1) s += __shfl_xor_sync(0xffffffffu, s, off);
    if (lane == 0) dinv[bh * Nn + n] = 1.f / s;
}

// global mean pool: out[b][c] = mean_n atoms[b*Nn+n][c]
__global__ void pool_k(const float* __restrict__ atoms, float* __restrict__ out) {
    int b = blockIdx.x, c = threadIdx.x;
    const float* p = atoms + (long)b * Nn * C + c;
    float s = 0.f;
    for (int n = 0; n < Nn; n++) s += p[(long)n * C];
    out[b * C + c] = s * (1.f / Nn);
}

// ---------------------------------------------------------------------------
// Host launcher
// ---------------------------------------------------------------------------
template<int BN_, int MODE, int ACT>
static inline void launch_gemm(const float* A, const float* B, const float* bias,
                               const float* rs, float* Cm,
                               int Mr, int Nc, int K, int lda, int ldb, int ldc,
                               int batch = 1, long sA = 0, long sB = 0, long sC = 0,
                               long sRS = 0) {
    dim3 grid((Nc + BN_ - 1) / BN_, (Mr + 127) / 128, batch);
    gemm_k<BN_, MODE, ACT><<<grid, 256>>>(A, B, bias, rs, Cm, Mr, Nc, K,
                                          lda, ldb, ldc, sA, sB, sC, sRS);
}

extern "C" void kernel_launch(void* const* d_in, const int* in_sizes, int n_in,
                              void* d_out, int out_size) {
    const float* x          = (const float*)d_in[0];
    const float* edge_attr  = (const float*)d_in[1];
    const int*   edge_index = (const int*)d_in[2];
    // d_in[3] = batch (unused; equal-sized graphs)
    const float* node_w = (const float*)d_in[4];
    const float* node_b = (const float*)d_in[5];
    const float* edge_w = (const float*)d_in[6];
    const float* edge_b = (const float*)d_in[7];
    const float* gw1 = (const float*)d_in[8];
    const float* gb1 = (const float*)d_in[9];
    const float* gw2 = (const float*)d_in[10];
    const float* gb2 = (const float*)d_in[11];
    const float* qw  = (const float*)d_in[12];
    const float* kw  = (const float*)d_in[13];
    const float* vw  = (const float*)d_in[14];
    const float* ow  = (const float*)d_in[15];
    const float* obv = (const float*)d_in[16];
    const float* proj = (const float*)d_in[17];
    const float* n1g = (const float*)d_in[18];
    const float* n1b = (const float*)d_in[19];
    const float* n2g = (const float*)d_in[20];
    const float* n2b = (const float*)d_in[21];
    const float* n3g = (const float*)d_in[22];
    const float* n3b = (const float*)d_in[23];
    const float* mw1 = (const float*)d_in[24];
    const float* mb1 = (const float*)d_in[25];
    const float* mw2 = (const float*)d_in[26];
    const float* mb2 = (const float*)d_in[27];

    float* S = nullptr;
    cudaGetSymbolAddress((void**)&S, g_scratch);
    float* atoms = S + OFF_ATOMS;
    float* ea    = S + OFF_EA;
    float* hbuf  = S + OFF_H;
    float* t1    = S + OFF_T1;
    float* tmp   = S + OFF_TMP;
    float* hloc  = S + OFF_HLOC;
    float* qb = S + OFF_Q, *kb = S + OFF_K, *vb = S + OFF_V;
    float* qr = S + OFF_QR, *kr = S + OFF_KR, *vr = S + OFF_VR;
    float* qp = S + OFF_QP, *kp = S + OFF_KP;
    float* ksum = S + OFF_KSUM;
    float* ctx  = S + OFF_CTX;
    float* dinv = S + OFF_DINV;
    float* attr = S + OFF_ATTR;
    float* att  = S + OFF_ATT;
    float* hatt = S + OFF_HATT;
    float* outb = S + OFF_OUT;
    float* xl   = S + OFF_XL;

    // node embedding: atoms = log1p(x) @ node_w + node_b
    { int n = TNn * 11; log1p_k<<<(n + 255) / 256, 256>>>(x, xl, n); }
    launch_gemm<128, 0, 0>(xl, node_w, node_b, nullptr, atoms, TNn, C, 11, 11, C, C);
    // edge embedding: ea = edge_attr @ edge_w + edge_b
    launch_gemm<128, 0, 0>(edge_attr, edge_w, edge_b, nullptr, ea, E, C, 4, 4, C, C);

    const long n4 = SZ_NC / 4;
    const int ew_blocks = (int)((n4 + 255) / 256);

    for (int l = 0; l < L; l++) {
        const float* gw1l = gw1 + (long)l * C * C;  const float* gb1l = gb1 + l * C;
        const float* gw2l = gw2 + (long)l * C * C;  const float* gb2l = gb2 + l * C;
        const float* qwl = qw + (long)l * C * C;
        const float* kwl = kw + (long)l * C * C;
        const float* vwl = vw + (long)l * C * C;
        const float* owl = ow + (long)l * C * C;    const float* obl = obv + l * C;
        const float* projl = proj + (long)l * MF * DH;
        const float* mw1l = mw1 + (long)l * C * C2; const float* mb1l = mb1 + l * C2;
        const float* mw2l = mw2 + (long)l * C2 * C; const float* mb2l = mb2 + l * C;

        // ---- GINEConv: h = atoms + scatter_sum(relu(atoms[src] + ea)) ----
        copy_k<<<ew_blocks, 256>>>(hbuf, atoms, n4);
        scatter_k<<<(E * 32) / 256, 256>>>(atoms, ea, edge_index, hbuf);
        launch_gemm<128, 0, 1>(hbuf, gw1l, gb1l, nullptr, t1, TNn, C, C, C, C, C);
        launch_gemm<128, 0, 0>(t1, gw2l, gb2l, nullptr, tmp, TNn, C, C, C, C, C);
        add_ln_k<<<TNn * 32 / 256, 256>>>(tmp, atoms, n1g + l * C, n1b + l * C, hloc);

        // ---- Performer attention ----
        launch_gemm<128, 0, 0>(atoms, qwl, nullptr, nullptr, qb, TNn, C, C, C, C, C);
        launch_gemm<128, 0, 0>(atoms, kwl, nullptr, nullptr, kb, TNn, C, C, C, C, C);
        launch_gemm<128, 0, 0>(atoms, vwl, nullptr, nullptr, vb, TNn, C, C, C, C, C);
        permute_qkv_k<<<(int)(SZ_NC / 256), 256>>>(qb, kb, vb, qr, kr, vr);
        // qp/kp[bh][512][266] = relu(qr @ proj^T) + 1e-3   (NT batched)
        launch_gemm<128, 1, 2>(qr, projl, nullptr, nullptr, qp, Nn, MF, DH, DH, DH, MF,
                               NBH, (long)Nn * DH, 0, (long)Nn * MF, 0);
        launch_gemm<128, 1, 2>(kr, projl, nullptr, nullptr, kp, Nn, MF, DH, DH, DH, MF,
                               NBH, (long)Nn * DH, 0, (long)Nn * MF, 0);
        ksum_k<<<dim3((MF + 255) / 256, NBH), 256>>>(kp, ksum);
        // ctx[bh][266][64] = kp^T @ vr   (TN batched)
        launch_gemm<64, 2, 0>(kp, vr, nullptr, nullptr, ctx, MF, DH, Nn, MF, DH, DH,
                              NBH, (long)Nn * MF, (long)Nn * DH, (long)MF * DH, 0);
        dinv_k<<<dim3(Nn / 8, NBH), 256>>>(qp, ksum, dinv);
        // attr[bh][512][64] = dinv ⊙ (qp @ ctx)   (NN batched, row-scale epilogue)
        launch_gemm<64, 0, 3>(qp, ctx, nullptr, dinv, attr, Nn, DH, MF, MF, DH, DH,
                              NBH, (long)Nn * MF, (long)MF * DH, (long)Nn * DH, (long)Nn);
        permute_att_k<<<(int)(SZ_NC / 256), 256>>>(attr, att);
        launch_gemm<128, 0, 0>(att, owl, obl, nullptr, tmp, TNn, C, C, C, C, C);
        add_ln_k<<<TNn * 32 / 256, 256>>>(tmp, atoms, n2g + l * C, n2b + l * C, hatt);

        // ---- combine + residual MLP + final norm ----
        add_k<<<ew_blocks, 256>>>(hloc, hatt, outb, n4);
        launch_gemm<128, 0, 1>(outb, mw1l, mb1l, nullptr, t1, TNn, C2, C, C, C2, C2);
        launch_gemm<128, 0, 0>(t1, mw2l, mb2l, nullptr, tmp, TNn, C, C2, C2, C, C);
        add_ln_k<<<TNn * 32 / 256, 256>>>(outb, tmp, n3g + l * C, n3b + l * C, atoms);
    }

    pool_k<<<Bg, 256>>>(atoms, (float*)d_out);
}

// round 13
// speedup vs baseline: 1.7556x; 1.7556x over previous
#include <cuda_runtime.h>
#include <math.h>
#include <stdint.h>

// ---------------------------------------------------------------------------
// Problem constants
// ---------------------------------------------------------------------------
namespace {
constexpr int TNn = 32768;   // total nodes  (B*N)
constexpr int C   = 256;     // channels
constexpr int E   = 524288;  // edges
constexpr int Bg  = 64;      // graphs
constexpr int Nn  = 512;     // nodes per graph
constexpr int H   = 4;       // heads
constexpr int DH  = 64;      // head dim
constexpr int MF  = 266;     // Performer random features
constexpr int C2  = 512;     // MLP hidden
constexpr int L   = 5;       // layers
constexpr int NBH = Bg * H;  // 256 attention batches

// scratch layout (floats)
constexpr long SZ_NC    = (long)TNn * C;                 // 8,388,608
constexpr long OFF_ATOMS = 0;
constexpr long OFF_EA    = OFF_ATOMS + SZ_NC;
constexpr long OFF_H     = OFF_EA + (long)E * C;
constexpr long OFF_T1    = OFF_H + SZ_NC;
constexpr long OFF_TMP   = OFF_T1 + (long)TNn * C2;
constexpr long OFF_HLOC  = OFF_TMP + SZ_NC;
constexpr long OFF_Q     = OFF_HLOC + SZ_NC;
constexpr long OFF_K     = OFF_Q + SZ_NC;
constexpr long OFF_V     = OFF_K + SZ_NC;
constexpr long OFF_QR    = OFF_V + SZ_NC;
constexpr long OFF_KR    = OFF_QR + SZ_NC;
constexpr long OFF_VR    = OFF_KR + SZ_NC;
constexpr long OFF_QP    = OFF_VR + SZ_NC;
constexpr long OFF_KP    = OFF_QP + (long)NBH * Nn * MF;
constexpr long OFF_KSUM  = OFF_KP + (long)NBH * Nn * MF;
constexpr long OFF_CTX   = OFF_KSUM + (long)NBH * MF;
constexpr long OFF_DINV  = OFF_CTX + (long)NBH * MF * DH;
constexpr long OFF_ATTR  = OFF_DINV + (long)NBH * Nn;
constexpr long OFF_ATT   = OFF_ATTR + SZ_NC;
constexpr long OFF_HATT  = OFF_ATT + SZ_NC;
constexpr long OFF_OUT   = OFF_HATT + SZ_NC;
constexpr long OFF_XL    = OFF_OUT + SZ_NC;
// transposed weights
constexpr long W_CC  = (long)L * C * C;      // 327,680
constexpr long W_CC2 = (long)L * C * C2;     // 655,360
constexpr long OFF_WG1 = OFF_XL + (long)TNn * 11;
constexpr long OFF_WG2 = OFF_WG1 + W_CC;
constexpr long OFF_WQ  = OFF_WG2 + W_CC;
constexpr long OFF_WK  = OFF_WQ + W_CC;
constexpr long OFF_WV  = OFF_WK + W_CC;
constexpr long OFF_WO  = OFF_WV + W_CC;
constexpr long OFF_WM1 = OFF_WO + W_CC;
constexpr long OFF_WM2 = OFF_WM1 + W_CC2;
constexpr long SCRATCH_TOTAL = OFF_WM2 + W_CC2;
}  // namespace

__device__ float g_scratch[SCRATCH_TOTAL];   // static scratch (no cudaMalloc)

// ---------------------------------------------------------------------------
// TF32 helpers
// ---------------------------------------------------------------------------
__device__ __forceinline__ unsigned f2tf32(float x) {
    unsigned r;
    asm("cvt.rna.tf32.f32 %0, %1;" : "=r"(r) : "f"(x));
    return r;
}

__device__ __forceinline__ void mma_tf32(float* c, const unsigned* a, const unsigned* b) {
    asm volatile(
        "mma.sync.aligned.m16n8k8.row.col.f32.tf32.tf32.f32 "
        "{%0,%1,%2,%3}, {%4,%5,%6,%7}, {%8,%9}, {%0,%1,%2,%3};"
        : "+f"(c[0]), "+f"(c[1]), "+f"(c[2]), "+f"(c[3])
        : "r"(a[0]), "r"(a[1]), "r"(a[2]), "r"(a[3]), "r"(b[0]), "r"(b[1]));
}

// ---------------------------------------------------------------------------
// TF32 tensor-core GEMM.
//   C[M][N] = act( A ? B + bias )
//   TA=0: A is [M][K] row-major.   TA=1: A is [K][M] row-major (transposed load).
//   TB=0: B is [N][K] row-major.   TB=1: B is [K][N] row-major (transposed load).
//   ACT: 0 none, 1 exact GELU, 2 relu+1e-3, 3 per-row scale (rs).
//   Batched via gridDim.z with element strides sA/sB/sC/sRS.
//   BM=128, BN_ in {128,64}, BK=16, 256 threads (8 warps, warp tile 64 x BN_/4).
// ---------------------------------------------------------------------------
template<int BN_, int TA, int TB, int ACT>
__global__ __launch_bounds__(256)
void mma_gemm_k(const float* __restrict__ A, const float* __restrict__ Bm,
                const float* __restrict__ bias, const float* __restrict__ rs,
                float* __restrict__ Cm,
                int Mr, int Nc, int K, int lda, int ldb, int ldc,
                long sA, long sB, long sC, long sRS)
{
    constexpr int BM = 128, BK = 16, SK = BK + 4;
    constexpr int NTile = BN_ / 32;           // mma n-tiles per warp: 4 or 2
    constexpr int NVB = BN_ * BK / 256;       // B floats per thread: 8 or 4

    const int z = blockIdx.z;
    A  += (long)z * sA;
    Bm += (long)z * sB;
    Cm += (long)z * sC;

    __shared__ float As[2][BM * SK];
    __shared__ float Bs[2][BN_ * SK];

    const int tid = threadIdx.x;
    const int wid = tid >> 5, lane = tid & 31;
    const int g = lane >> 2, tg = lane & 3;
    const int wm = (wid >> 2) * 64;
    const int wn = (wid & 3) * (BN_ / 4);
    const int rowBase = blockIdx.y * BM;
    const int colBase = blockIdx.x * BN_;

    float acc[4][NTile][4];
    #pragma unroll
    for (int a = 0; a < 4; a++)
        #pragma unroll
        for (int b = 0; b < NTile; b++)
            #pragma unroll
            for (int c = 0; c < 4; c++) acc[a][b][c] = 0.f;

    unsigned aReg[8], bReg[NVB];
    const bool vecA = ((lda & 3) == 0);
    const bool vecB = ((ldb & 3) == 0);

    auto loadA = [&](int kt) {
        if (TA == 0) {
            int ar = tid >> 1, ak = (tid & 1) * 8;
            int gm = rowBase + ar;
            bool rok = gm < Mr;
            const float* ap = A + (long)gm * lda + kt + ak;
            if (rok && vecA && (kt + ak + 8 <= K)) {
                float4 v0 = *(const float4*)ap;
                float4 v1 = *(const float4*)(ap + 4);
                aReg[0] = f2tf32(v0.x); aReg[1] = f2tf32(v0.y);
                aReg[2] = f2tf32(v0.z); aReg[3] = f2tf32(v0.w);
                aReg[4] = f2tf32(v1.x); aReg[5] = f2tf32(v1.y);
                aReg[6] = f2tf32(v1.z); aReg[7] = f2tf32(v1.w);
            } else {
                #pragma unroll
                for (int i = 0; i < 8; i++) {
                    int gk = kt + ak + i;
                    float v = (rok && gk < K) ? ap[i] : 0.f;
                    aReg[i] = f2tf32(v);
                }
            }
        } else {   // A is [K][M]
            int kr = tid & 15, r0 = (tid >> 4) * 8;
            int gk = kt + kr;
            bool kok = gk < K;
            const float* ap = A + (long)gk * lda + rowBase + r0;
            #pragma unroll
            for (int i = 0; i < 8; i++) {
                int gm = rowBase + r0 + i;
                float v = (kok && gm < Mr) ? ap[i] : 0.f;
                aReg[i] = f2tf32(v);
            }
        }
    };
    auto storeA = [&](int s) {
        if (TA == 0) {
            int ar = tid >> 1, ak = (tid & 1) * 8;
            unsigned* p = (unsigned*)&As[s][ar * SK + ak];
            *(uint4*)p       = make_uint4(aReg[0], aReg[1], aReg[2], aReg[3]);
            *(uint4*)(p + 4) = make_uint4(aReg[4], aReg[5], aReg[6], aReg[7]);
        } else {
            int kr = tid & 15, r0 = (tid >> 4) * 8;
            unsigned* p = (unsigned*)As[s];
            #pragma unroll
            for (int i = 0; i < 8; i++) p[(r0 + i) * SK + kr] = aReg[i];
        }
    };
    auto loadB = [&](int kt) {
        if (TB == 0) {           // B is [N][K]
            if (BN_ == 128) {
                int br = tid >> 1, bk = (tid & 1) * 8;
                int gn = colBase + br;
                bool nok = gn < Nc;
                const float* bp = Bm + (long)gn * ldb + kt + bk;
                if (nok && vecB && (kt + bk + 8 <= K)) {
                    float4 v0 = *(const float4*)bp;
                    float4 v1 = *(const float4*)(bp + 4);
                    bReg[0] = f2tf32(v0.x); bReg[1] = f2tf32(v0.y);
                    bReg[2] = f2tf32(v0.z); bReg[3] = f2tf32(v0.w);
                    bReg[4] = f2tf32(v1.x); bReg[5] = f2tf32(v1.y);
                    bReg[6] = f2tf32(v1.z); bReg[7] = f2tf32(v1.w);
                } else {
                    #pragma unroll
                    for (int i = 0; i < 8; i++) {
                        int gk = kt + bk + i;
                        float v = (nok && gk < K) ? bp[i] : 0.f;
                        bReg[i] = f2tf32(v);
                    }
                }
            } else {             // BN_ == 64: one float4 per thread
                int br = tid >> 2, bk = (tid & 3) * 4;
                int gn = colBase + br;
                bool nok = gn < Nc;
                const float* bp = Bm + (long)gn * ldb + kt + bk;
                if (nok && vecB && (kt + bk + 4 <= K)) {
                    float4 v0 = *(const float4*)bp;
                    bReg[0] = f2tf32(v0.x); bReg[1] = f2tf32(v0.y);
                    bReg[2] = f2tf32(v0.z); bReg[3] = f2tf32(v0.w);
                } else {
                    #pragma unroll
                    for (int i = 0; i < 4; i++) {
                        int gk = kt + bk + i;
                        float v = (nok && gk < K) ? bp[i] : 0.f;
                        bReg[i] = f2tf32(v);
                    }
                }
            }
        } else {                 // B is [K][N]
            constexpr int PER = BN_ / 16;  // 8 or 4
            int kr = tid & 15, n0 = (tid >> 4) * PER;
            int gk = kt + kr;
            bool kok = gk < K;
            const float* bp = Bm + (long)gk * ldb + colBase + n0;
            #pragma unroll
            for (int i = 0; i < PER; i++) {
                int gn = colBase + n0 + i;
                float v = (kok && gn < Nc) ? bp[i] : 0.f;
                bReg[i] = f2tf32(v);
            }
        }
    };
    auto storeB = [&](int s) {
        if (TB == 0) {
            if (BN_ == 128) {
                int br = tid >> 1, bk = (tid & 1) * 8;
                unsigned* p = (unsigned*)&Bs[s][br * SK + bk];
                *(uint4*)p       = make_uint4(bReg[0], bReg[1], bReg[2], bReg[3]);
                *(uint4*)(p + 4) = make_uint4(bReg[4], bReg[5], bReg[6], bReg[7]);
            } else {
                int br = tid >> 2, bk = (tid & 3) * 4;
                unsigned* p = (unsigned*)&Bs[s][br * SK + bk];
                *(uint4*)p = make_uint4(bReg[0], bReg[1], bReg[2], bReg[3]);
            }
        } else {
            constexpr int PER = BN_ / 16;
            int kr = tid & 15, n0 = (tid >> 4) * PER;
            unsigned* p = (unsigned*)Bs[s];
            #pragma unroll
            for (int i = 0; i < PER; i++) p[(n0 + i) * SK + kr] = bReg[i];
        }
    };

    const int nk = (K + BK - 1) / BK;

    loadA(0); loadB(0);
    storeA(0); storeB(0);
    __syncthreads();

    for (int it = 0; it < nk; it++) {
        int s = it & 1;
        if (it + 1 < nk) { loadA((it + 1) * BK); loadB((it + 1) * BK); }

        const unsigned* asu = (const unsigned*)As[s];
        const unsigned* bsu = (const unsigned*)Bs[s];
        #pragma unroll
        for (int ks = 0; ks < 2; ks++) {
            const int kk = ks * 8;
            unsigned af[4][4];
            #pragma unroll
            for (int mt = 0; mt < 4; mt++) {
                int m = wm + mt * 16 + g;
                af[mt][0] = asu[m * SK + kk + tg];
                af[mt][1] = asu[(m + 8) * SK + kk + tg];
                af[mt][2] = asu[m * SK + kk + tg + 4];
                af[mt][3] = asu[(m + 8) * SK + kk + tg + 4];
            }
            unsigned bf[NTile][2];
            #pragma unroll
            for (int nt = 0; nt < NTile; nt++) {
                int n = wn + nt * 8 + g;
                bf[nt][0] = bsu[n * SK + kk + tg];
                bf[nt][1] = bsu[n * SK + kk + tg + 4];
            }
            #pragma unroll
            for (int mt = 0; mt < 4; mt++)
                #pragma unroll
                for (int nt = 0; nt < NTile; nt++)
                    mma_tf32(acc[mt][nt], af[mt], bf[nt]);
        }

        if (it + 1 < nk) { storeA(s ^ 1); storeB(s ^ 1); }
        __syncthreads();
    }

    // ---- epilogue ----
    #pragma unroll
    for (int mt = 0; mt < 4; mt++) {
        #pragma unroll
        for (int hh = 0; hh < 2; hh++) {
            int gm = rowBase + wm + mt * 16 + g + hh * 8;
            if (gm >= Mr) continue;
            float scale = 1.f;
            if (ACT == 3) scale = rs[(long)z * sRS + gm];
            float* crow = Cm + (long)gm * ldc;
            #pragma unroll
            for (int nt = 0; nt < NTile; nt++) {
                int gn = colBase + wn + nt * 8 + 2 * tg;
                #pragma unroll
                for (int q = 0; q < 2; q++) {
                    if (gn + q >= Nc) continue;
                    float v = acc[mt][nt][hh * 2 + q];
                    if (bias) v += bias[gn + q];
                    if (ACT == 1)      v = v * normcdff(v);
                    else if (ACT == 2) v = fmaxf(v, 0.f) + 1e-3f;
                    else if (ACT == 3) v *= scale;
                    crow[gn + q] = v;
                }
            }
        }
    }
}

// ---------------------------------------------------------------------------
// Small-K FFMA GEMM for embeddings (K=11 / K=4).  NN: A[M][K], B[K][N].
// ---------------------------------------------------------------------------
__global__ __launch_bounds__(256)
void gemm_small_k(const float* __restrict__ A, const float* __restrict__ Bm,
                  const float* __restrict__ bias, float* __restrict__ Cm,
                  int Mr, int K)
{
    // N = 256 fixed.
    constexpr int BM = 128;
    __shared__ float Bsh[16 * 256];   // up to K=16
    __shared__ float Ash[BM * 16];
    const int tid = threadIdx.x;
    const int rowBase = blockIdx.y * BM;
    for (int i = tid; i < K * 256; i += 256) Bsh[i] = Bm[i];
    for (int i = tid; i < BM * K; i += 256) {
        int r = i / K, c = i % K;
        int gm = rowBase + r;
        Ash[r * 16 + c] = (gm < Mr) ? A[(long)gm * K + c] : 0.f;
    }
    __syncthreads();
    int txc = (tid & 15) * 16;       // col base
    int tyr = (tid >> 4) * 8;        // row base
    float accv[8][16];
    #pragma unroll
    for (int i = 0; i < 8; i++)
        #pragma unroll
        for (int j = 0; j < 16; j++) accv[i][j] = 0.f;
    for (int k = 0; k < K; k++) {
        float bvals[16];
        #pragma unroll
        for (int j = 0; j < 16; j++) bvals[j] = Bsh[k * 256 + txc + j];
        #pragma unroll
        for (int i = 0; i < 8; i++) {
            float a = Ash[(tyr + i) * 16 + k];
            #pragma unroll
            for (int j = 0; j < 16; j++) accv[i][j] = fmaf(a, bvals[j], accv[i][j]);
        }
    }
    #pragma unroll
    for (int i = 0; i < 8; i++) {
        int gm = rowBase + tyr + i;
        if (gm >= Mr) continue;
        float* crow = Cm + (long)gm * 256;
        #pragma unroll
        for (int j = 0; j < 16; j++) crow[txc + j] = accv[i][j] + bias[txc + j];
    }
}

// ---------------------------------------------------------------------------
// Elementwise / reduction kernels
// ---------------------------------------------------------------------------
__global__ void log1p_k(const float* __restrict__ x, float* __restrict__ o, int n) {
    int i = blockIdx.x * 256 + threadIdx.x;
    if (i < n) o[i] = log1pf(x[i]);
}

__global__ void copy_k(float* __restrict__ dst, const float* __restrict__ src, long n4) {
    long i = blockIdx.x * 256L + threadIdx.x;
    if (i < n4) ((float4*)dst)[i] = ((const float4*)src)[i];
}

__global__ void add_k(const float* __restrict__ a, const float* __restrict__ b,
                      float* __restrict__ o, long n4) {
    long i = blockIdx.x * 256L + threadIdx.x;
    if (i < n4) {
        float4 x = ((const float4*)a)[i], y = ((const float4*)b)[i];
        x.x += y.x; x.y += y.y; x.z += y.z; x.w += y.w;
        ((float4*)o)[i] = x;
    }
}

// weight transpose [K][N] -> [N][K], batched over layers via z.
__global__ void wtrans_k(const float* __restrict__ in, float* __restrict__ out,
                         int K, int N) {
    __shared__ float t[32][33];
    long zoff = (long)blockIdx.z * K * N;
    int n0 = blockIdx.x * 32, k0 = blockIdx.y * 32;
    int x = threadIdx.x, y = threadIdx.y;     // 32 x 8
    #pragma unroll
    for (int i = 0; i < 32; i += 8) {
        int k = k0 + y + i, n = n0 + x;
        t[y + i][x] = (k < K && n < N) ? in[zoff + (long)k * N + n] : 0.f;
    }
    __syncthreads();
    #pragma unroll
    for (int i = 0; i < 32; i += 8) {
        int n = n0 + y + i, k = k0 + x;
        if (n < N && k < K) out[zoff + (long)n * K + k] = t[x][y + i];
    }
}

// GINE message + scatter-add: aggr[dst] += relu(atoms[src] + ea[e])
__global__ __launch_bounds__(256)
void scatter_k(const float* __restrict__ atoms, const float* __restrict__ ea,
               const int* __restrict__ ei, float* __restrict__ aggr) {
    int gidx = blockIdx.x * 256 + threadIdx.x;
    int e = gidx >> 5, lane = gidx & 31;
    if (e >= E) return;
    int s = ei[e];
    int d = ei[E + e];
    const float4* ar = reinterpret_cast<const float4*>(atoms + (long)s * C) + lane * 2;
    const float4* er = reinterpret_cast<const float4*>(ea + (long)e * C) + lane * 2;
    float* out = aggr + (long)d * C + lane * 8;
    #pragma unroll
    for (int t = 0; t < 2; t++) {
        float4 a = ar[t], ev = er[t];
        float m;
        m = a.x + ev.x; if (m > 0.f) atomicAdd(out + t * 4 + 0, m);
        m = a.y + ev.y; if (m > 0.f) atomicAdd(out + t * 4 + 1, m);
        m = a.z + ev.z; if (m > 0.f) atomicAdd(out + t * 4 + 2, m);
        m = a.w + ev.w; if (m > 0.f) atomicAdd(out + t * 4 + 3, m);
    }
}

// out = LayerNorm(a + b) * g + be   (one warp per row of C=256)
__global__ __launch_bounds__(256)
void add_ln_k(const float* __restrict__ a, const float* __restrict__ b,
              const float* __restrict__ g, const float* __restrict__ be,
              float* __restrict__ o) {
    int w = (blockIdx.x * 256 + threadIdx.x) >> 5;
    int lane = threadIdx.x & 31;
    if (w >= TNn) return;
    const float* ar = a + (long)w * C;
    const float* br = b + (long)w * C;
    float v[8]; float s = 0.f, s2 = 0.f;
    #pragma unroll
    for (int i = 0; i < 8; i++) {
        int c = lane + i * 32;
        float t = ar[c] + br[c];
        v[i] = t; s += t; s2 += t * t;
    }
    #pragma unroll
    for (int off = 16; off; off >>= 1) {
        s  += __shfl_xor_sync(0xffffffffu, s, off);
        s2 += __shfl_xor_sync(0xffffffffu, s2, off);
    }
    float mu = s * (1.f / C);
    float var = s2 * (1.f / C) - mu * mu;
    float rstd = rsqrtf(var + 1e-5f);
    float* orow = o + (long)w * C;
    #pragma unroll
    for (int i = 0; i < 8; i++) {
        int c = lane + i * 32;
        orow[c] = (v[i] - mu) * rstd * g[c] + be[c];
    }
}

// [TN, H*DH] -> [bh][n][d] for q,k,v at once
__global__ void permute_qkv_k(const float* __restrict__ q, const float* __restrict__ k,
                              const float* __restrict__ v,
                              float* __restrict__ qr, float* __restrict__ kr,
                              float* __restrict__ vr) {
    long i = blockIdx.x * 256L + threadIdx.x;
    if (i >= SZ_NC) return;
    int d = (int)(i & 63);
    long t = i >> 6;
    int n = (int)(t % Nn); t /= Nn;
    int h = (int)(t % H);
    int b = (int)(t / H);
    long src = ((long)b * Nn + n) * C + h * DH + d;
    qr[i] = q[src]; kr[i] = k[src]; vr[i] = v[src];
}

// [bh][n][d] -> [TN, H*DH]
__global__ void permute_att_k(const float* __restrict__ attr, float* __restrict__ att) {
    long i = blockIdx.x * 256L + threadIdx.x;   // dest index
    if (i >= SZ_NC) return;
    int c = (int)(i & (C - 1));
    long r = i >> 8;
    int n = (int)(r % Nn);
    int b = (int)(r / Nn);
    int h = c >> 6;
    int d = c & 63;
    long src = (((long)(b * H + h)) * Nn + n) * DH + d;
    att[i] = attr[src];
}

// ksum[bh][m] = sum_n kp[bh][n][m]
__global__ void ksum_k(const float* __restrict__ kp, float* __restrict__ ks) {
    int bh = blockIdx.y;
    int m = blockIdx.x * 256 + threadIdx.x;
    if (m >= MF) return;
    const float* p = kp + (long)bh * Nn * MF + m;
    float s = 0.f;
    for (int n = 0; n < Nn; n++) s += p[(long)n * MF];
    ks[bh * MF + m] = s;
}

// dinv[bh][n] = 1 / dot(qp[bh][n][:], ksum[bh][:])
__global__ __launch_bounds__(256)
void dinv_k(const float* __restrict__ qp, const float* __restrict__ ks,
            float* __restrict__ dinv) {
    __shared__ float kss[MF];
    int bh = blockIdx.y;
    for (int m = threadIdx.x; m < MF; m += 256) kss[m] = ks[bh * MF + m];
    __syncthreads();
    int warp = threadIdx.x >> 5, lane = threadIdx.x & 31;
    int n = blockIdx.x * 8 + warp;
    const float* q = qp + ((long)bh * Nn + n) * MF;
    float s = 0.f;
    for (int m = lane; m < MF; m += 32) s += q[m] * kss[m];
    #pragma unroll
    for (int off = 16; off; off >>= 1) s += __shfl_xor_sync(0xffffffffu, s, off);
    if (lane == 0) dinv[bh * Nn + n] = 1.f / s;
}

// global mean pool: out[b][c] = mean_n atoms[b*Nn+n][c]
__global__ void pool_k(const float* __restrict__ atoms, float* __restrict__ out) {
    int b = blockIdx.x, c = threadIdx.x;
    const float* p = atoms + (long)b * Nn * C + c;
    float s = 0.f;
    for (int n = 0; n < Nn; n++) s += p[(long)n * C];
    out[b * C + c] = s * (1.f / Nn);
}

// ---------------------------------------------------------------------------
// Host launchers
// ---------------------------------------------------------------------------
template<int BN_, int TA, int TB, int ACT>
static inline void launch_mma(const float* A, const float* B, const float* bias,
                              const float* rs, float* Cm,
                              int Mr, int Nc, int K, int lda, int ldb, int ldc,
                              int batch = 1, long sA = 0, long sB = 0, long sC = 0,
                              long sRS = 0) {
    dim3 grid((Nc + BN_ - 1) / BN_, (Mr + 127) / 128, batch);
    mma_gemm_k<BN_, TA, TB, ACT><<<grid, 256>>>(A, B, bias, rs, Cm, Mr, Nc, K,
                                                lda, ldb, ldc, sA, sB, sC, sRS);
}

extern "C" void kernel_launch(void* const* d_in, const int* in_sizes, int n_in,
                              void* d_out, int out_size) {
    const float* x          = (const float*)d_in[0];
    const float* edge_attr  = (const float*)d_in[1];
    const int*   edge_index = (const int*)d_in[2];
    const float* node_w = (const float*)d_in[4];
    const float* node_b = (const float*)d_in[5];
    const float* edge_w = (const float*)d_in[6];
    const float* edge_b = (const float*)d_in[7];
    const float* gw1 = (const float*)d_in[8];
    const float* gb1 = (const float*)d_in[9];
    const float* gw2 = (const float*)d_in[10];
    const float* gb2 = (const float*)d_in[11];
    const float* qw  = (const float*)d_in[12];
    const float* kw  = (const float*)d_in[13];
    const float* vw  = (const float*)d_in[14];
    const float* ow  = (const float*)d_in[15];
    const float* obv = (const float*)d_in[16];
    const float* proj = (const float*)d_in[17];
    const float* n1g = (const float*)d_in[18];
    const float* n1b = (const float*)d_in[19];
    const float* n2g = (const float*)d_in[20];
    const float* n2b = (const float*)d_in[21];
    const float* n3g = (const float*)d_in[22];
    const float* n3b = (const float*)d_in[23];
    const float* mw1 = (const float*)d_in[24];
    const float* mb1 = (const float*)d_in[25];
    const float* mw2 = (const float*)d_in[26];
    const float* mb2 = (const float*)d_in[27];

    float* S = nullptr;
    cudaGetSymbolAddress((void**)&S, g_scratch);
    float* atoms = S + OFF_ATOMS;
    float* ea    = S + OFF_EA;
    float* hbuf  = S + OFF_H;
    float* t1    = S + OFF_T1;
    float* tmp   = S + OFF_TMP;
    float* hloc  = S + OFF_HLOC;
    float* qb = S + OFF_Q, *kb = S + OFF_K, *vb = S + OFF_V;
    float* qr = S + OFF_QR, *kr = S + OFF_KR, *vr = S + OFF_VR;
    float* qpb = S + OFF_QP, *kpb = S + OFF_KP;
    float* ksum = S + OFF_KSUM;
    float* ctxT = S + OFF_CTX;
    float* dinv = S + OFF_DINV;
    float* attr = S + OFF_ATTR;
    float* att  = S + OFF_ATT;
    float* hatt = S + OFF_HATT;
    float* outb = S + OFF_OUT;
    float* xl   = S + OFF_XL;
    float* WG1 = S + OFF_WG1, *WG2 = S + OFF_WG2;
    float* WQ = S + OFF_WQ, *WK = S + OFF_WK, *WV = S + OFF_WV, *WO = S + OFF_WO;
    float* WM1 = S + OFF_WM1, *WM2 = S + OFF_WM2;

    // ---- pre-transpose all weights to [N][K] (once per launch, ~10us) ----
    {
        dim3 blk(32, 8);
        dim3 gCC(C / 32, C / 32, L);
        wtrans_k<<<gCC, blk>>>(gw1, WG1, C, C);
        wtrans_k<<<gCC, blk>>>(gw2, WG2, C, C);
        wtrans_k<<<gCC, blk>>>(qw, WQ, C, C);
        wtrans_k<<<gCC, blk>>>(kw, WK, C, C);
        wtrans_k<<<gCC, blk>>>(vw, WV, C, C);
        wtrans_k<<<gCC, blk>>>(ow, WO, C, C);
        dim3 gM1(C2 / 32, C / 32, L);
        wtrans_k<<<gM1, blk>>>(mw1, WM1, C, C2);   // [C][C2] -> [C2][C]
        dim3 gM2(C / 32, C2 / 32, L);
        wtrans_k<<<gM2, blk>>>(mw2, WM2, C2, C);   // [C2][C] -> [C][C2]
    }

    // node embedding: atoms = log1p(x) @ node_w + node_b   (K=11)
    { int n = TNn * 11; log1p_k<<<(n + 255) / 256, 256>>>(x, xl, n); }
    gemm_small_k<<<dim3(1, TNn / 128), 256>>>(xl, node_w, node_b, atoms, TNn, 11);
    // edge embedding: ea = edge_attr @ edge_w + edge_b     (K=4)
    gemm_small_k<<<dim3(1, E / 128), 256>>>(edge_attr, edge_w, edge_b, ea, E, 4);

    const long n4 = SZ_NC / 4;
    const int ew_blocks = (int)((n4 + 255) / 256);

    for (int l = 0; l < L; l++) {
        const float* gb1l = gb1 + l * C;
        const float* gb2l = gb2 + l * C;
        const float* obl  = obv + l * C;
        const float* projl = proj + (long)l * MF * DH;
        const float* mb1l = mb1 + l * C2;
        const float* mb2l = mb2 + l * C;
        const float* WG1l = WG1 + (long)l * C * C;
        const float* WG2l = WG2 + (long)l * C * C;
        const float* WQl = WQ + (long)l * C * C;
        const float* WKl = WK + (long)l * C * C;
        const float* WVl = WV + (long)l * C * C;
        const float* WOl = WO + (long)l * C * C;
        const float* WM1l = WM1 + (long)l * C * C2;
        const float* WM2l = WM2 + (long)l * C * C2;

        // ---- GINEConv: h = atoms + scatter_sum(relu(atoms[src] + ea)) ----
        copy_k<<<ew_blocks, 256>>>(hbuf, atoms, n4);
        scatter_k<<<(E * 32) / 256, 256>>>(atoms, ea, edge_index, hbuf);
        launch_mma<128, 0, 0, 1>(hbuf, WG1l, gb1l, nullptr, t1, TNn, C, C, C, C, C);
        launch_mma<128, 0, 0, 0>(t1, WG2l, gb2l, nullptr, tmp, TNn, C, C, C, C, C);
        add_ln_k<<<TNn * 32 / 256, 256>>>(tmp, atoms, n1g + l * C, n1b + l * C, hloc);

        // ---- Performer attention ----
        launch_mma<128, 0, 0, 0>(atoms, WQl, nullptr, nullptr, qb, TNn, C, C, C, C, C);
        launch_mma<128, 0, 0, 0>(atoms, WKl, nullptr, nullptr, kb, TNn, C, C, C, C, C);
        launch_mma<128, 0, 0, 0>(atoms, WVl, nullptr, nullptr, vb, TNn, C, C, C, C, C);
        permute_qkv_k<<<(int)(SZ_NC / 256), 256>>>(qb, kb, vb, qr, kr, vr);
        // qp/kp[bh][512][266] = relu(qr @ proj^T) + 1e-3   (NT batched)
        launch_mma<64, 0, 0, 2>(qr, projl, nullptr, nullptr, qpb, Nn, MF, DH,
                                DH, DH, MF, NBH, (long)Nn * DH, 0, (long)Nn * MF, 0);
        launch_mma<64, 0, 0, 2>(kr, projl, nullptr, nullptr, kpb, Nn, MF, DH,
                                DH, DH, MF, NBH, (long)Nn * DH, 0, (long)Nn * MF, 0);
        ksum_k<<<dim3((MF + 255) / 256, NBH), 256>>>(kpb, ksum);
        // ctxT[bh][64][266] = vr^T @ kp  (both transposed loads)
        launch_mma<64, 1, 1, 0>(vr, kpb, nullptr, nullptr, ctxT, DH, MF, Nn,
                                DH, MF, MF, NBH, (long)Nn * DH, (long)Nn * MF,
                                (long)DH * MF, 0);
        dinv_k<<<dim3(Nn / 8, NBH), 256>>>(qpb, ksum, dinv);
        // attr[bh][512][64] = dinv o (qp @ ctxT^T)   (NT, row-scale epilogue)
        launch_mma<64, 0, 0, 3>(qpb, ctxT, nullptr, dinv, attr, Nn, DH, MF,
                                MF, MF, DH, NBH, (long)Nn * MF, (long)DH * MF,
                                (long)Nn * DH, (long)Nn);
        permute_att_k<<<(int)(SZ_NC / 256), 256>>>(attr, att);
        launch_mma<128, 0, 0, 0>(att, WOl, obl, nullptr, tmp, TNn, C, C, C, C, C);
        add_ln_k<<<TNn * 32 / 256, 256>>>(tmp, atoms, n2g + l * C, n2b + l * C, hatt);

        // ---- combine + residual MLP + final norm ----
        add_k<<<ew_blocks, 256>>>(hloc, hatt, outb, n4);
        launch_mma<128, 0, 0, 1>(outb, WM1l, mb1l, nullptr, t1, TNn, C2, C, C, C, C2);
        launch_mma<128, 0, 0, 0>(t1, WM2l, mb2l, nullptr, tmp, TNn, C, C2, C2, C2, C);
        add_ln_k<<<TNn * 32 / 256, 256>>>(outb, tmp, n3g + l * C, n3b + l * C, atoms);
    }

    pool_k<<<Bg, 256>>>(atoms, (float*)d_out);
}